// round 1
// baseline (speedup 1.0000x reference)
#include <cuda_runtime.h>
#include <math.h>
#include <stdint.h>

// Problem constants
#define NNODE 128
#define NEDGE 4096
#define DFEAT 130          // D = N + 2
#define HDIM  64
#define DH    8320         // D * H
#define KSL   13           // k-slices for msg1
#define KPS   640          // k per slice (13*640 = 8320)

// ---------------- scratch (device globals; no runtime allocation) -------------
__device__ float g_G1[(size_t)NNODE * DH * HDIM];          // 272.6 MB  [n][k][o]
__device__ float g_msgPart[(size_t)KSL * NEDGE * HDIM];    // 13.6 MB   [slice][e][o]
__device__ float g_c1[NNODE * HDIM];
__device__ float g_h1[NNODE * HDIM];
__device__ float g_G2[NNODE * HDIM * HDIM];                // 4 MB [n][k][o]
__device__ float g_c2[NNODE * HDIM];
__device__ float g_msg2[NEDGE * HDIM];
__device__ float g_h2[NNODE * HDIM];
__device__ int   g_srcOff[NNODE + 1];
__device__ int   g_dstOff[NNODE + 1];
__device__ int   g_srcSorted[NEDGE];
__device__ int   g_dstSorted[NEDGE];

// ---------------- edge bucketing (deterministic) ------------------------------
__global__ void k_offsets(const int* __restrict__ ei) {
    int n = threadIdx.x;   // 128 threads
    int cs = 0, cd = 0;
    for (int e = 0; e < NEDGE; e++) {
        cs += (ei[e] == n);
        cd += (ei[NEDGE + e] == n);
    }
    __shared__ int ss[NNODE + 1], sd[NNODE + 1];
    ss[n + 1] = cs; sd[n + 1] = cd;
    if (n == 0) { ss[0] = 0; sd[0] = 0; }
    __syncthreads();
    for (int off = 1; off < NNODE; off <<= 1) {
        int vs = 0, vd = 0;
        if (n + 1 > off) { vs = ss[n + 1 - off]; vd = sd[n + 1 - off]; }
        __syncthreads();
        ss[n + 1] += vs; sd[n + 1] += vd;
        __syncthreads();
    }
    g_srcOff[n + 1] = ss[n + 1];
    g_dstOff[n + 1] = sd[n + 1];
    if (n == 0) { g_srcOff[0] = 0; g_dstOff[0] = 0; }
}

__global__ void k_fill(const int* __restrict__ ei) {
    int t = threadIdx.x;            // 256 threads: 0..127 src, 128..255 dst
    int n = t & 127;
    if (t < NNODE) {
        int pos = g_srcOff[n];
        for (int e = 0; e < NEDGE; e++)
            if (ei[e] == n) g_srcSorted[pos++] = e;
    } else {
        int pos = g_dstOff[n];
        for (int e = 0; e < NEDGE; e++)
            if (ei[NEDGE + e] == n) g_dstSorted[pos++] = e;
    }
}

// ---------------- Phase A: G1[n,k,o] = sum_i x[n,i] * W1b[k, i*64+o] ----------
#define SMEM_G1 ((DFEAT * NNODE + DFEAT * HDIM) * 4)   // 99840 bytes

__global__ void __launch_bounds__(256, 2) k_G1(const float* __restrict__ x,
                                               const float* __restrict__ W1b) {
    extern __shared__ float sm[];
    float* Xs = sm;                  // [130][128]  x transposed
    float* Ws = sm + DFEAT * NNODE;  // [130][64]   W1b row for this k
    int k = blockIdx.x;

    for (int idx = threadIdx.x; idx < NNODE * DFEAT; idx += 256) {
        int n = idx / DFEAT, i = idx - n * DFEAT;
        Xs[i * NNODE + n] = x[idx];
    }
    const float* wr = W1b + (size_t)k * DH;
    for (int idx = threadIdx.x; idx < DH; idx += 256) Ws[idx] = wr[idx];
    __syncthreads();

    int tn = threadIdx.x >> 3;        // 0..31 -> rows tn*4 .. tn*4+3
    int to = threadIdx.x & 7;         // cols  to*8 .. to*8+7
    float acc[4][8];
#pragma unroll
    for (int a = 0; a < 4; a++)
#pragma unroll
        for (int b = 0; b < 8; b++) acc[a][b] = 0.f;

    for (int i = 0; i < DFEAT; ++i) {
        float4 xv = *(const float4*)(Xs + i * NNODE + tn * 4);
        float4 wa = *(const float4*)(Ws + i * HDIM + to * 8);
        float4 wb = *(const float4*)(Ws + i * HDIM + to * 8 + 4);
        float xs4[4] = {xv.x, xv.y, xv.z, xv.w};
        float ws8[8] = {wa.x, wa.y, wa.z, wa.w, wb.x, wb.y, wb.z, wb.w};
#pragma unroll
        for (int a = 0; a < 4; a++)
#pragma unroll
            for (int b = 0; b < 8; b++)
                acc[a][b] = fmaf(xs4[a], ws8[b], acc[a][b]);
    }

#pragma unroll
    for (int a = 0; a < 4; a++) {
        int n = tn * 4 + a;
        float* dst = g_G1 + ((size_t)n * DH + k) * HDIM + to * 8;
        *(float4*)dst       = make_float4(acc[a][0], acc[a][1], acc[a][2], acc[a][3]);
        *(float4*)(dst + 4) = make_float4(acc[a][4], acc[a][5], acc[a][6], acc[a][7]);
    }
}

// ---------------- c1[n,o] = sum_i x[n,i] * b1b[i*64+o] ------------------------
__global__ void k_c1(const float* __restrict__ x, const float* __restrict__ b1b) {
    int n = blockIdx.x, o = threadIdx.x;   // 64 threads
    __shared__ float xs[DFEAT];
    for (int i = o; i < DFEAT; i += HDIM) xs[i] = x[n * DFEAT + i];
    __syncthreads();
    float a = 0.f;
    for (int i = 0; i < DFEAT; i++) a = fmaf(xs[i], b1b[i * HDIM + o], a);
    g_c1[n * HDIM + o] = a;
}

// ---------------- Phase B: per-src-group edge contraction ---------------------
// msgPart[sl][e][o] = sum_{k in slice} relu(ea_e*w1a[k]+b1a[k]) * G1[src_e][k][o]
__global__ void __launch_bounds__(256) k_msg1(const float* __restrict__ ea,
                                              const float* __restrict__ W1a,
                                              const float* __restrict__ b1a) {
    int n = blockIdx.x, sl = blockIdx.y;
    int beg = g_srcOff[n];
    int m = g_srcOff[n + 1] - beg;
    if (m == 0) return;

    __shared__ float eaS[32];
    __shared__ int   eidS[32];
    __shared__ float Gs[16 * 64];
    __shared__ float uS[32 * 16];

    int e8 = threadIdx.x >> 3;           // edge slot 0..31
    int og = (threadIdx.x & 7) * 8;      // o base
    const float* Gbase = g_G1 + (size_t)n * DH * HDIM;
    int kc0 = sl * KPS;

    for (int t0 = 0; t0 < m; t0 += 32) {
        __syncthreads();   // protect eidS/eaS vs previous tile's use
        if (threadIdx.x < 32) {
            int j = t0 + threadIdx.x;
            if (j < m) {
                int eid = g_srcSorted[beg + j];
                eidS[threadIdx.x] = eid;
                eaS[threadIdx.x] = ea[eid];
            } else {
                eidS[threadIdx.x] = 0;
                eaS[threadIdx.x] = 0.f;
            }
        }
        float acc[8] = {0, 0, 0, 0, 0, 0, 0, 0};
        for (int kc = kc0; kc < kc0 + KPS; kc += 16) {
            __syncthreads();   // Gs/uS reuse + eaS ready on first iter
            const float4* gsrc = (const float4*)(Gbase + (size_t)kc * HDIM);
            ((float4*)Gs)[threadIdx.x] = gsrc[threadIdx.x];   // 1024 floats
#pragma unroll
            for (int r = 0; r < 2; r++) {
                int id2 = threadIdx.x + r * 256;
                int ue = id2 >> 4, uk = id2 & 15;
                uS[id2] = fmaxf(fmaf(eaS[ue], W1a[kc + uk], b1a[kc + uk]), 0.f);
            }
            __syncthreads();
#pragma unroll
            for (int kk = 0; kk < 16; kk++) {
                float u = uS[e8 * 16 + kk];
                float4 ga = *(float4*)(Gs + kk * 64 + og);
                float4 gb = *(float4*)(Gs + kk * 64 + og + 4);
                acc[0] = fmaf(u, ga.x, acc[0]);
                acc[1] = fmaf(u, ga.y, acc[1]);
                acc[2] = fmaf(u, ga.z, acc[2]);
                acc[3] = fmaf(u, ga.w, acc[3]);
                acc[4] = fmaf(u, gb.x, acc[4]);
                acc[5] = fmaf(u, gb.y, acc[5]);
                acc[6] = fmaf(u, gb.z, acc[6]);
                acc[7] = fmaf(u, gb.w, acc[7]);
            }
        }
        if (t0 + e8 < m) {
            float* dst = g_msgPart + ((size_t)sl * NEDGE + eidS[e8]) * HDIM + og;
            *(float4*)dst       = make_float4(acc[0], acc[1], acc[2], acc[3]);
            *(float4*)(dst + 4) = make_float4(acc[4], acc[5], acc[6], acc[7]);
        }
    }
}

// ------------- agg (mean over dst) + root weight + bias + relu -> h1 ---------
__global__ void k_agg_h1(const int* __restrict__ ei, const float* __restrict__ x,
                         const float* __restrict__ Wr1, const float* __restrict__ bc1) {
    int n = blockIdx.x, o = threadIdx.x;   // 64 threads
    __shared__ float xs[DFEAT];
    for (int i = o; i < DFEAT; i += HDIM) xs[i] = x[n * DFEAT + i];
    int beg = g_dstOff[n];
    int m = g_dstOff[n + 1] - beg;
    float a = 0.f;
    for (int j = 0; j < m; j++) {
        int e = g_dstSorted[beg + j];
        float v = g_c1[ei[e] * HDIM + o];
#pragma unroll
        for (int s = 0; s < KSL; s++)
            v += g_msgPart[((size_t)s * NEDGE + e) * HDIM + o];
        a += v;
    }
    a /= fmaxf((float)m, 1.f);
    __syncthreads();
    float r = bc1[o];
    for (int i = 0; i < DFEAT; i++) r = fmaf(xs[i], Wr1[i * HDIM + o], r);
    g_h1[n * HDIM + o] = fmaxf(a + r, 0.f);
}

// ------------- conv2 pre-contraction: G2[n,k,o], c2[n,o] ----------------------
__global__ void k_G2c2(const float* __restrict__ W2b, const float* __restrict__ b2b) {
    int n = blockIdx.x;
    __shared__ float hs[HDIM];
    if (threadIdx.x < HDIM) hs[threadIdx.x] = g_h1[n * HDIM + threadIdx.x];
    __syncthreads();
    int k = threadIdx.x >> 2;           // 0..63
    int ob = (threadIdx.x & 3) * 16;    // 16 outputs
    float acc[16];
#pragma unroll
    for (int j = 0; j < 16; j++) acc[j] = 0.f;
    for (int i = 0; i < HDIM; i++) {
        float hv = hs[i];
        const float4* wr = (const float4*)(W2b + (size_t)k * (HDIM * HDIM) + i * HDIM + ob);
#pragma unroll
        for (int q = 0; q < 4; q++) {
            float4 w4 = wr[q];
            acc[q * 4 + 0] = fmaf(hv, w4.x, acc[q * 4 + 0]);
            acc[q * 4 + 1] = fmaf(hv, w4.y, acc[q * 4 + 1]);
            acc[q * 4 + 2] = fmaf(hv, w4.z, acc[q * 4 + 2]);
            acc[q * 4 + 3] = fmaf(hv, w4.w, acc[q * 4 + 3]);
        }
    }
    float* dst = g_G2 + ((size_t)n * HDIM + k) * HDIM + ob;
#pragma unroll
    for (int j = 0; j < 16; j++) dst[j] = acc[j];
    if (threadIdx.x < HDIM) {
        int o = threadIdx.x;
        float c = 0.f;
        for (int i = 0; i < HDIM; i++) c = fmaf(hs[i], b2b[i * HDIM + o], c);
        g_c2[n * HDIM + o] = c;
    }
}

// ------------- conv2 per-edge message ----------------------------------------
__global__ void k_msg2(const int* __restrict__ ei, const float* __restrict__ ea,
                       const float* __restrict__ W2a, const float* __restrict__ b2a) {
    int e = blockIdx.x, o = threadIdx.x;   // 64 threads
    int s = ei[e];
    float a_ = ea[e];
    __shared__ float u2[HDIM];
    u2[o] = fmaxf(fmaf(a_, W2a[o], b2a[o]), 0.f);
    __syncthreads();
    float acc = g_c2[s * HDIM + o];
    const float* G2 = g_G2 + (size_t)s * HDIM * HDIM;
#pragma unroll 8
    for (int k = 0; k < HDIM; k++) acc = fmaf(u2[k], G2[k * HDIM + o], acc);
    g_msg2[e * HDIM + o] = acc;
}

// ------------- conv2 aggregation + root + relu -> h2 --------------------------
__global__ void k_agg2_h2(const float* __restrict__ Wr2, const float* __restrict__ bc2) {
    int n = blockIdx.x, o = threadIdx.x;   // 64 threads
    __shared__ float hs[HDIM];
    hs[o] = g_h1[n * HDIM + o];
    int beg = g_dstOff[n];
    int m = g_dstOff[n + 1] - beg;
    float a = 0.f;
    for (int j = 0; j < m; j++) {
        int e = g_dstSorted[beg + j];
        a += g_msg2[e * HDIM + o];
    }
    a /= fmaxf((float)m, 1.f);
    __syncthreads();
    float r = bc2[o];
    for (int i = 0; i < HDIM; i++) r = fmaf(hs[i], Wr2[i * HDIM + o], r);
    g_h2[n * HDIM + o] = fmaxf(a + r, 0.f);
}

// ------------- output head: logits -> masked softmax -> packet mask ----------
__global__ void k_out(const int* __restrict__ adj, const float* __restrict__ npk,
                      const float* __restrict__ Wout, const float* __restrict__ bout,
                      float* __restrict__ out) {
    int n = blockIdx.x, j = threadIdx.x;   // 128 threads
    __shared__ float hs[HDIM];
    __shared__ float red[NNODE];
    if (j < HDIM) hs[j] = g_h2[n * HDIM + j];
    __syncthreads();
    float l = bout[j];
    for (int o = 0; o < HDIM; o++) l = fmaf(hs[o], Wout[o * NNODE + j], l);
    bool a = (adj[n * NNODE + j] != 0);
    const float NEGINF = __int_as_float(0xff800000);
    red[j] = a ? l : NEGINF;
    __syncthreads();
    for (int s = 64; s > 0; s >>= 1) {
        if (j < s) red[j] = fmaxf(red[j], red[j + s]);
        __syncthreads();
    }
    float mx = red[0];
    __syncthreads();
    float p = a ? expf(l - mx) : 0.f;
    red[j] = p;
    __syncthreads();
    for (int s = 64; s > 0; s >>= 1) {
        if (j < s) red[j] += red[j + s];
        __syncthreads();
    }
    float sum = red[0];
    float pr = p / sum;
    bool msk = (npk[n] != -1.0f);
    out[n * NNODE + j] = msk ? pr : (j == n ? 1.f : 0.f);
}

// ------------------------------ launcher --------------------------------------
extern "C" void kernel_launch(void* const* d_in, const int* in_sizes, int n_in,
                              void* d_out, int out_size) {
    const float* x    = (const float*)d_in[0];
    const int*   ei   = (const int*)  d_in[1];
    const float* ea   = (const float*)d_in[2];
    const int*   adj  = (const int*)  d_in[3];
    const float* npk  = (const float*)d_in[4];
    const float* W1a  = (const float*)d_in[5];
    const float* b1a  = (const float*)d_in[6];
    const float* W1b  = (const float*)d_in[7];
    const float* b1b  = (const float*)d_in[8];
    const float* Wr1  = (const float*)d_in[9];
    const float* bc1  = (const float*)d_in[10];
    const float* W2a  = (const float*)d_in[11];
    const float* b2a  = (const float*)d_in[12];
    const float* W2b  = (const float*)d_in[13];
    const float* b2b  = (const float*)d_in[14];
    const float* Wr2  = (const float*)d_in[15];
    const float* bc2  = (const float*)d_in[16];
    const float* Wout = (const float*)d_in[17];
    const float* bout = (const float*)d_in[18];
    float* out = (float*)d_out;

    cudaFuncSetAttribute(k_G1, cudaFuncAttributeMaxDynamicSharedMemorySize, SMEM_G1);

    k_offsets<<<1, 128>>>(ei);
    k_fill<<<1, 256>>>(ei);
    k_G1<<<DH, 256, SMEM_G1>>>(x, W1b);
    k_c1<<<NNODE, HDIM>>>(x, b1b);
    k_msg1<<<dim3(NNODE, KSL), 256>>>(ea, W1a, b1a);
    k_agg_h1<<<NNODE, HDIM>>>(ei, x, Wr1, bc1);
    k_G2c2<<<NNODE, 256>>>(W2b, b2b);
    k_msg2<<<NEDGE, HDIM>>>(ei, ea, W2a, b2a);
    k_agg2_h2<<<NNODE, HDIM>>>(Wr2, bc2);
    k_out<<<NNODE, NNODE>>>(adj, npk, Wout, bout, out);
}

// round 2
// speedup vs baseline: 2.3595x; 2.3595x over previous
#include <cuda_runtime.h>
#include <math.h>
#include <stdint.h>

// Problem constants
#define NNODE 128
#define NEDGE 4096
#define DFEAT 130          // D = N + 2
#define HDIM  64
#define DH    8320         // D * H
#define VCH   8            // chunks for variable-prefix scan
#define BCH   8            // chunks for baseline reduction
#define MAXROWS (DH + VCH) // 8328

// ---------------- scratch (device globals; no runtime allocation) -------------
__device__ float g_SLs[(size_t)MAXROWS * DH];   // 277 MB  local prefix (w-weighted)
__device__ float g_SLq[(size_t)MAXROWS * DH];   // 277 MB  local prefix (b-weighted)
__device__ float g_BpS[BCH][DH], g_BpQ[BCH][DH];
__device__ float g_TotS[VCH][DH], g_TotQ[VCH][DH];
__device__ float g_OffS[VCH][DH], g_OffQ[VCH][DH];
__device__ unsigned long long g_key[DH];
__device__ float g_tS[DH], g_cw[DH], g_cb[DH];
__device__ int   g_kS[DH], g_kB[DH];
__device__ int   g_cntV, g_cntB, g_L;
__device__ int   g_j[NEDGE];
__device__ float g_msg1[NEDGE * HDIM];
__device__ float g_c1[NNODE * HDIM];
__device__ float g_h1[NNODE * HDIM];
__device__ float g_G2[NNODE * HDIM * HDIM];
__device__ float g_c2[NNODE * HDIM];
__device__ float g_msg2[NEDGE * HDIM];
__device__ float g_h2[NNODE * HDIM];
__device__ int   g_srcOff[NNODE + 1];
__device__ int   g_dstOff[NNODE + 1];
__device__ int   g_srcSorted[NEDGE];
__device__ int   g_dstSorted[NEDGE];

// ---------------- edge bucketing (deterministic) ------------------------------
__global__ void k_offsets(const int* __restrict__ ei) {
    int n = threadIdx.x;   // 128 threads
    int cs = 0, cd = 0;
    for (int e = 0; e < NEDGE; e++) {
        cs += (ei[e] == n);
        cd += (ei[NEDGE + e] == n);
    }
    __shared__ int ss[NNODE + 1], sd[NNODE + 1];
    ss[n + 1] = cs; sd[n + 1] = cd;
    if (n == 0) { ss[0] = 0; sd[0] = 0; }
    __syncthreads();
    for (int off = 1; off < NNODE; off <<= 1) {
        int vs = 0, vd = 0;
        if (n + 1 > off) { vs = ss[n + 1 - off]; vd = sd[n + 1 - off]; }
        __syncthreads();
        ss[n + 1] += vs; sd[n + 1] += vd;
        __syncthreads();
    }
    g_srcOff[n + 1] = ss[n + 1];
    g_dstOff[n + 1] = sd[n + 1];
    if (n == 0) { g_srcOff[0] = 0; g_dstOff[0] = 0; }
}

__global__ void k_fill(const int* __restrict__ ei) {
    int t = threadIdx.x;            // 256 threads: 0..127 src, 128..255 dst
    int n = t & 127;
    if (t < NNODE) {
        int pos = g_srcOff[n];
        for (int e = 0; e < NEDGE; e++)
            if (ei[e] == n) g_srcSorted[pos++] = e;
    } else {
        int pos = g_dstOff[n];
        for (int e = 0; e < NEDGE; e++)
            if (ei[NEDGE + e] == n) g_dstSorted[pos++] = e;
    }
}

// ------------- classify k's: always / variable (t in (0,1)) / never ----------
// baseline list = always-active  U  negative-slope variable (active at a=0-)
__global__ void k_classify(const float* __restrict__ W1a, const float* __restrict__ b1a) {
    __shared__ int sV[256], sB[256];
    __shared__ int baseV, baseB;
    int tid = threadIdx.x;
    if (tid == 0) { baseV = 0; baseB = 0; }
    __syncthreads();
    for (int chunk = 0; chunk < (DH + 255) / 256; chunk++) {
        int k = chunk * 256 + tid;
        bool valid = (k < DH);
        int isV = 0, isB = 0;
        float t = 2.f;
        if (valid) {
            float w = W1a[k], b = b1a[k];
            if (w > 0.f) {
                t = -b / w;
                isV = (t > 0.f && t < 1.f);
                isB = (t <= 0.f);                 // always active on [0,1)
            } else if (w < 0.f) {
                t = -b / w;
                isV = (t > 0.f && t < 1.f);
                isB = (t >= 1.f) || isV;          // always OR active below its threshold
            } else {
                isB = (b > 0.f);
            }
        }
        sV[tid] = isV; sB[tid] = isB;
        __syncthreads();
        for (int off = 1; off < 256; off <<= 1) {
            int av = 0, ab = 0;
            if (tid >= off) { av = sV[tid - off]; ab = sB[tid - off]; }
            __syncthreads();
            sV[tid] += av; sB[tid] += ab;
            __syncthreads();
        }
        if (valid && isV) {
            int pos = baseV + sV[tid] - 1;
            g_key[pos] = ((unsigned long long)__float_as_uint(t) << 32) | (unsigned)k;
        }
        if (valid && isB) {
            int pos = baseB + sB[tid] - 1;
            g_kB[pos] = k;
        }
        __syncthreads();
        if (tid == 255) { baseV += sV[255]; baseB += sB[255]; }
        __syncthreads();
    }
    if (tid == 0) {
        g_cntV = baseV;
        g_cntB = baseB;
        g_L = (baseV + VCH) / VCH;   // ceil((V+1)/VCH)
    }
}

// ------------- bitonic sort variable entries by (t, k); gather coeffs --------
#define SORT_N 16384
__global__ void k_sort(const float* __restrict__ W1a, const float* __restrict__ b1a) {
    extern __shared__ unsigned long long key[];
    int tid = threadIdx.x;   // 1024 threads
    int V = g_cntV;
    for (int i = tid; i < SORT_N; i += 1024)
        key[i] = (i < V) ? g_key[i] : 0xFFFFFFFFFFFFFFFFull;
    __syncthreads();
    for (int size = 2; size <= SORT_N; size <<= 1) {
        for (int stride = size >> 1; stride > 0; stride >>= 1) {
            for (int i = tid; i < SORT_N; i += 1024) {
                int jj = i ^ stride;
                if (jj > i) {
                    bool up = ((i & size) == 0);
                    unsigned long long a = key[i], b = key[jj];
                    if ((a > b) == up) { key[i] = b; key[jj] = a; }
                }
            }
            __syncthreads();
        }
    }
    for (int i = tid; i < V; i += 1024) {
        unsigned long long kv = key[i];
        int k = (int)(kv & 0xFFFFFFFFull);
        float t = __uint_as_float((unsigned)(kv >> 32));
        float w = W1a[k], b = b1a[k];
        g_tS[i] = t;
        g_kS[i] = k;
        if (w > 0.f) { g_cw[i] = w;  g_cb[i] = b;  }   // activates when crossed
        else         { g_cw[i] = -w; g_cb[i] = -b; }   // deactivates when crossed
    }
}

// ------------- baseline partial sums over baseline list (chunked) ------------
__global__ void k_baseline(const float* __restrict__ W1a, const float* __restrict__ b1a,
                           const float* __restrict__ W1b) {
    int col = blockIdx.x * 128 + threadIdx.x;   // 65 x 128 = 8320
    int c = blockIdx.y;
    int nB = g_cntB;
    int lo = (c * nB) / BCH, hi = ((c + 1) * nB) / BCH;
    float s = 0.f, q = 0.f;
    for (int r = lo; r < hi; r++) {
        int k = g_kB[r];
        float v = W1b[(size_t)k * DH + col];
        s = fmaf(W1a[k], v, s);
        q = fmaf(b1a[k], v, q);
    }
    g_BpS[c][col] = s;
    g_BpQ[c][col] = q;
}

// ------------- chunked local prefix scan over sorted variable entries --------
__global__ void k_prefix(const float* __restrict__ W1b) {
    int col = blockIdx.x * 128 + threadIdx.x;
    int c = blockIdx.y;
    int L = g_L, V = g_cntV;
    float s = 0.f, q = 0.f;
    for (int jl = 0; jl < L; jl++) {
        int j = c * L + jl;
        size_t ro = (size_t)j * DH + col;
        g_SLs[ro] = s;           // prefix EXCLUDING entry j
        g_SLq[ro] = q;
        if (j < V) {
            int k = g_kS[j];
            float v = W1b[(size_t)k * DH + col];
            s = fmaf(g_cw[j], v, s);
            q = fmaf(g_cb[j], v, q);
        }
    }
    g_TotS[c][col] = s;
    g_TotQ[c][col] = q;
}

// ------------- combine baseline + chunk totals into per-chunk offsets --------
__global__ void k_off() {
    int col = blockIdx.x * 128 + threadIdx.x;
    float sS = 0.f, sQ = 0.f;
    for (int bc = 0; bc < BCH; bc++) { sS += g_BpS[bc][col]; sQ += g_BpQ[bc][col]; }
    float oS = sS, oQ = sQ;
    for (int c = 0; c < VCH; c++) {
        g_OffS[c][col] = oS;
        g_OffQ[c][col] = oQ;
        oS += g_TotS[c][col];
        oQ += g_TotQ[c][col];
    }
}

// ------------- per-edge position: j = #(t <= a) -------------------------------
__global__ void k_edgej(const float* __restrict__ ea) {
    int e = blockIdx.x * 256 + threadIdx.x;
    if (e >= NEDGE) return;
    float a = ea[e];
    int lo = 0, hi = g_cntV;
    while (lo < hi) {
        int mid = (lo + hi) >> 1;
        if (g_tS[mid] <= a) lo = mid + 1; else hi = mid;
    }
    g_j[e] = lo;
}

// ---------------- c1[n,o] = sum_i x[n,i] * b1b[i*64+o] ------------------------
__global__ void k_c1(const float* __restrict__ x, const float* __restrict__ b1b) {
    int n = blockIdx.x, o = threadIdx.x;   // 64 threads
    __shared__ float xs[DFEAT];
    for (int i = o; i < DFEAT; i += HDIM) xs[i] = x[n * DFEAT + i];
    __syncthreads();
    float a = 0.f;
    for (int i = 0; i < DFEAT; i++) a = fmaf(xs[i], b1b[i * HDIM + o], a);
    g_c1[n * HDIM + o] = a;
}

// ------------- conv1 per-edge message via prefix rows -------------------------
// msg_e[o] = sum_i x[src,i] * ( a*(SL[j]+Off[c]) + (QL[j]+OffQ[c]) )[i*64+o] + c1[src,o]
__global__ void __launch_bounds__(128) k_msg1(const int* __restrict__ ei,
                                              const float* __restrict__ ea,
                                              const float* __restrict__ x) {
    int e = blockIdx.x;
    int tid = threadIdx.x;
    int src = ei[e];
    float a = ea[e];
    int j = g_j[e];
    int c = j / g_L;

    __shared__ float xs[DFEAT];
    __shared__ float rs[128], rq[128];
    for (int i = tid; i < DFEAT; i += 128) xs[i] = x[src * DFEAT + i];
    __syncthreads();

    int half = tid >> 6;
    int o = tid & 63;
    const float* Srow = g_SLs + (size_t)j * DH;
    const float* Qrow = g_SLq + (size_t)j * DH;
    const float* OfS = g_OffS[c];
    const float* OfQ = g_OffQ[c];

    float ss = 0.f, qq = 0.f;
    for (int i = half; i < DFEAT; i += 2) {
        int m = i * HDIM + o;
        float xi = xs[i];
        ss = fmaf(xi, Srow[m] + OfS[m], ss);
        qq = fmaf(xi, Qrow[m] + OfQ[m], qq);
    }
    rs[tid] = ss; rq[tid] = qq;
    __syncthreads();
    if (tid < 64) {
        float S = rs[tid] + rs[tid + 64];
        float Q = rq[tid] + rq[tid + 64];
        g_msg1[e * HDIM + tid] = fmaf(a, S, Q) + g_c1[src * HDIM + tid];
    }
}

// ------------- agg (mean over dst) + root weight + bias + relu -> h1 ---------
__global__ void k_agg_h1(const float* __restrict__ x,
                         const float* __restrict__ Wr1, const float* __restrict__ bc1) {
    int n = blockIdx.x, o = threadIdx.x;   // 64 threads
    __shared__ float xs[DFEAT];
    for (int i = o; i < DFEAT; i += HDIM) xs[i] = x[n * DFEAT + i];
    int beg = g_dstOff[n];
    int m = g_dstOff[n + 1] - beg;
    float a = 0.f;
    for (int jj = 0; jj < m; jj++) {
        int e = g_dstSorted[beg + jj];
        a += g_msg1[e * HDIM + o];
    }
    a /= fmaxf((float)m, 1.f);
    __syncthreads();
    float r = bc1[o];
    for (int i = 0; i < DFEAT; i++) r = fmaf(xs[i], Wr1[i * HDIM + o], r);
    g_h1[n * HDIM + o] = fmaxf(a + r, 0.f);
}

// ------------- conv2 pre-contraction: G2[n,k,o], c2[n,o] ----------------------
__global__ void k_G2c2(const float* __restrict__ W2b, const float* __restrict__ b2b) {
    int n = blockIdx.x;
    __shared__ float hs[HDIM];
    if (threadIdx.x < HDIM) hs[threadIdx.x] = g_h1[n * HDIM + threadIdx.x];
    __syncthreads();
    int k = threadIdx.x >> 2;
    int ob = (threadIdx.x & 3) * 16;
    float acc[16];
#pragma unroll
    for (int jj = 0; jj < 16; jj++) acc[jj] = 0.f;
    for (int i = 0; i < HDIM; i++) {
        float hv = hs[i];
        const float4* wr = (const float4*)(W2b + (size_t)k * (HDIM * HDIM) + i * HDIM + ob);
#pragma unroll
        for (int q = 0; q < 4; q++) {
            float4 w4 = wr[q];
            acc[q * 4 + 0] = fmaf(hv, w4.x, acc[q * 4 + 0]);
            acc[q * 4 + 1] = fmaf(hv, w4.y, acc[q * 4 + 1]);
            acc[q * 4 + 2] = fmaf(hv, w4.z, acc[q * 4 + 2]);
            acc[q * 4 + 3] = fmaf(hv, w4.w, acc[q * 4 + 3]);
        }
    }
    float* dst = g_G2 + ((size_t)n * HDIM + k) * HDIM + ob;
#pragma unroll
    for (int jj = 0; jj < 16; jj++) dst[jj] = acc[jj];
    if (threadIdx.x < HDIM) {
        int o = threadIdx.x;
        float cacc = 0.f;
        for (int i = 0; i < HDIM; i++) cacc = fmaf(hs[i], b2b[i * HDIM + o], cacc);
        g_c2[n * HDIM + o] = cacc;
    }
}

// ------------- conv2 per-edge message ----------------------------------------
__global__ void k_msg2(const int* __restrict__ ei, const float* __restrict__ ea,
                       const float* __restrict__ W2a, const float* __restrict__ b2a) {
    int e = blockIdx.x, o = threadIdx.x;   // 64 threads
    int s = ei[e];
    float a_ = ea[e];
    __shared__ float u2[HDIM];
    u2[o] = fmaxf(fmaf(a_, W2a[o], b2a[o]), 0.f);
    __syncthreads();
    float acc = g_c2[s * HDIM + o];
    const float* G2 = g_G2 + (size_t)s * HDIM * HDIM;
#pragma unroll 8
    for (int k = 0; k < HDIM; k++) acc = fmaf(u2[k], G2[k * HDIM + o], acc);
    g_msg2[e * HDIM + o] = acc;
}

// ------------- conv2 aggregation + root + relu -> h2 --------------------------
__global__ void k_agg2_h2(const float* __restrict__ Wr2, const float* __restrict__ bc2) {
    int n = blockIdx.x, o = threadIdx.x;   // 64 threads
    __shared__ float hs[HDIM];
    hs[o] = g_h1[n * HDIM + o];
    int beg = g_dstOff[n];
    int m = g_dstOff[n + 1] - beg;
    float a = 0.f;
    for (int jj = 0; jj < m; jj++) {
        int e = g_dstSorted[beg + jj];
        a += g_msg2[e * HDIM + o];
    }
    a /= fmaxf((float)m, 1.f);
    __syncthreads();
    float r = bc2[o];
    for (int i = 0; i < HDIM; i++) r = fmaf(hs[i], Wr2[i * HDIM + o], r);
    g_h2[n * HDIM + o] = fmaxf(a + r, 0.f);
}

// ------------- output head: logits -> masked softmax -> packet mask ----------
__global__ void k_out(const int* __restrict__ adj, const float* __restrict__ npk,
                      const float* __restrict__ Wout, const float* __restrict__ bout,
                      float* __restrict__ out) {
    int n = blockIdx.x, j = threadIdx.x;   // 128 threads
    __shared__ float hs[HDIM];
    __shared__ float red[NNODE];
    if (j < HDIM) hs[j] = g_h2[n * HDIM + j];
    __syncthreads();
    float l = bout[j];
    for (int o = 0; o < HDIM; o++) l = fmaf(hs[o], Wout[o * NNODE + j], l);
    bool a = (adj[n * NNODE + j] != 0);
    const float NEGINF = __int_as_float(0xff800000);
    red[j] = a ? l : NEGINF;
    __syncthreads();
    for (int s = 64; s > 0; s >>= 1) {
        if (j < s) red[j] = fmaxf(red[j], red[j + s]);
        __syncthreads();
    }
    float mx = red[0];
    __syncthreads();
    float p = a ? expf(l - mx) : 0.f;
    red[j] = p;
    __syncthreads();
    for (int s = 64; s > 0; s >>= 1) {
        if (j < s) red[j] += red[j + s];
        __syncthreads();
    }
    float sum = red[0];
    float pr = p / sum;
    bool msk = (npk[n] != -1.0f);
    out[n * NNODE + j] = msk ? pr : (j == n ? 1.f : 0.f);
}

// ------------------------------ launcher --------------------------------------
extern "C" void kernel_launch(void* const* d_in, const int* in_sizes, int n_in,
                              void* d_out, int out_size) {
    const float* x    = (const float*)d_in[0];
    const int*   ei   = (const int*)  d_in[1];
    const float* ea   = (const float*)d_in[2];
    const int*   adj  = (const int*)  d_in[3];
    const float* npk  = (const float*)d_in[4];
    const float* W1a  = (const float*)d_in[5];
    const float* b1a  = (const float*)d_in[6];
    const float* W1b  = (const float*)d_in[7];
    const float* b1b  = (const float*)d_in[8];
    const float* Wr1  = (const float*)d_in[9];
    const float* bc1  = (const float*)d_in[10];
    const float* W2a  = (const float*)d_in[11];
    const float* b2a  = (const float*)d_in[12];
    const float* W2b  = (const float*)d_in[13];
    const float* b2b  = (const float*)d_in[14];
    const float* Wr2  = (const float*)d_in[15];
    const float* bc2  = (const float*)d_in[16];
    const float* Wout = (const float*)d_in[17];
    const float* bout = (const float*)d_in[18];
    float* out = (float*)d_out;

    cudaFuncSetAttribute(k_sort, cudaFuncAttributeMaxDynamicSharedMemorySize,
                         SORT_N * (int)sizeof(unsigned long long));

    k_offsets<<<1, 128>>>(ei);
    k_fill<<<1, 256>>>(ei);
    k_classify<<<1, 256>>>(W1a, b1a);
    k_sort<<<1, 1024, SORT_N * sizeof(unsigned long long)>>>(W1a, b1a);
    k_baseline<<<dim3(65, BCH), 128>>>(W1a, b1a, W1b);
    k_prefix<<<dim3(65, VCH), 128>>>(W1b);
    k_off<<<65, 128>>>();
    k_edgej<<<16, 256>>>(ea);
    k_c1<<<NNODE, HDIM>>>(x, b1b);
    k_msg1<<<NEDGE, 128>>>(ei, ea, x);
    k_agg_h1<<<NNODE, HDIM>>>(x, Wr1, bc1);
    k_G2c2<<<NNODE, 256>>>(W2b, b2b);
    k_msg2<<<NEDGE, HDIM>>>(ei, ea, W2a, b2a);
    k_agg2_h2<<<NNODE, HDIM>>>(Wr2, bc2);
    k_out<<<NNODE, NNODE>>>(adj, npk, Wout, bout, out);
}

// round 3
// speedup vs baseline: 4.1072x; 1.7407x over previous
#include <cuda_runtime.h>
#include <math.h>
#include <stdint.h>

// Problem constants
#define NNODE 128
#define NEDGE 4096
#define DFEAT 130          // D = N + 2
#define HDIM  64
#define DH    8320         // D * H
#define VCH   16           // chunks for variable-prefix scan
#define BCH   32           // chunks for baseline reduction
#define MAXROWS (DH + 32)

// ---------------- scratch (device globals; no runtime allocation) -------------
__device__ float g_SLs[(size_t)MAXROWS * DH];   // local prefix (w-weighted)
__device__ float g_SLq[(size_t)MAXROWS * DH];   // local prefix (b-weighted)
__device__ float g_BpS[BCH][DH], g_BpQ[BCH][DH];
__device__ float g_TotS[VCH][DH], g_TotQ[VCH][DH];
__device__ float g_OffS[VCH][DH], g_OffQ[VCH][DH];
__device__ unsigned long long g_key[DH];
__device__ float g_tS[DH], g_cw[DH], g_cb[DH];
__device__ int   g_kS[DH], g_kB[DH];
__device__ int   g_cntV, g_cntB, g_L;
__device__ int   g_j[NEDGE];
__device__ float g_msg1[NEDGE * HDIM];
__device__ float g_c1[NNODE * HDIM];
__device__ float g_h1[NNODE * HDIM];
__device__ float g_G2[NNODE * HDIM * HDIM];
__device__ float g_c2[NNODE * HDIM];
__device__ float g_msg2[NEDGE * HDIM];
__device__ float g_h2[NNODE * HDIM];
__device__ int   g_srcOff[NNODE + 1];
__device__ int   g_dstOff[NNODE + 1];
__device__ int   g_srcSorted[NEDGE];
__device__ int   g_dstSorted[NEDGE];

// ---------------- edge bucketing (deterministic) ------------------------------
__global__ void k_offsets(const int* __restrict__ ei) {
    int n = threadIdx.x;   // 128 threads
    int cs = 0, cd = 0;
    for (int e = 0; e < NEDGE; e++) {
        cs += (ei[e] == n);
        cd += (ei[NEDGE + e] == n);
    }
    __shared__ int ss[NNODE + 1], sd[NNODE + 1];
    ss[n + 1] = cs; sd[n + 1] = cd;
    if (n == 0) { ss[0] = 0; sd[0] = 0; }
    __syncthreads();
    for (int off = 1; off < NNODE; off <<= 1) {
        int vs = 0, vd = 0;
        if (n + 1 > off) { vs = ss[n + 1 - off]; vd = sd[n + 1 - off]; }
        __syncthreads();
        ss[n + 1] += vs; sd[n + 1] += vd;
        __syncthreads();
    }
    g_srcOff[n + 1] = ss[n + 1];
    g_dstOff[n + 1] = sd[n + 1];
    if (n == 0) { g_srcOff[0] = 0; g_dstOff[0] = 0; }
}

__global__ void k_fill(const int* __restrict__ ei) {
    int t = threadIdx.x;            // 256 threads: 0..127 src, 128..255 dst
    int n = t & 127;
    if (t < NNODE) {
        int pos = g_srcOff[n];
        for (int e = 0; e < NEDGE; e++)
            if (ei[e] == n) g_srcSorted[pos++] = e;
    } else {
        int pos = g_dstOff[n];
        for (int e = 0; e < NEDGE; e++)
            if (ei[NEDGE + e] == n) g_dstSorted[pos++] = e;
    }
}

// ------------- classify k's: always / variable (t in (0,1)) / never ----------
__global__ void k_classify(const float* __restrict__ W1a, const float* __restrict__ b1a) {
    __shared__ int sV[256], sB[256];
    __shared__ int baseV, baseB;
    int tid = threadIdx.x;
    if (tid == 0) { baseV = 0; baseB = 0; }
    __syncthreads();
    for (int chunk = 0; chunk < (DH + 255) / 256; chunk++) {
        int k = chunk * 256 + tid;
        bool valid = (k < DH);
        int isV = 0, isB = 0;
        float t = 2.f;
        if (valid) {
            float w = W1a[k], b = b1a[k];
            if (w > 0.f) {
                t = -b / w;
                isV = (t > 0.f && t < 1.f);
                isB = (t <= 0.f);
            } else if (w < 0.f) {
                t = -b / w;
                isV = (t > 0.f && t < 1.f);
                isB = (t >= 1.f) || isV;
            } else {
                isB = (b > 0.f);
            }
        }
        sV[tid] = isV; sB[tid] = isB;
        __syncthreads();
        for (int off = 1; off < 256; off <<= 1) {
            int av = 0, ab = 0;
            if (tid >= off) { av = sV[tid - off]; ab = sB[tid - off]; }
            __syncthreads();
            sV[tid] += av; sB[tid] += ab;
            __syncthreads();
        }
        if (valid && isV) {
            int pos = baseV + sV[tid] - 1;
            g_key[pos] = ((unsigned long long)__float_as_uint(t) << 32) | (unsigned)k;
        }
        if (valid && isB) {
            int pos = baseB + sB[tid] - 1;
            g_kB[pos] = k;
        }
        __syncthreads();
        if (tid == 255) { baseV += sV[255]; baseB += sB[255]; }
        __syncthreads();
    }
    if (tid == 0) {
        g_cntV = baseV;
        g_cntB = baseB;
        g_L = (baseV + VCH) / VCH;
    }
}

// ------------- parallel rank-scatter (replaces bitonic sort) ------------------
__global__ void k_rank(const float* __restrict__ W1a, const float* __restrict__ b1a) {
    __shared__ unsigned long long tile[256];
    int V = g_cntV;
    int idx = blockIdx.x * 256 + threadIdx.x;
    unsigned long long my = (idx < V) ? g_key[idx] : 0xFFFFFFFFFFFFFFFFull;
    int r = 0;
    for (int t0 = 0; t0 < V; t0 += 256) {
        int ld = t0 + threadIdx.x;
        tile[threadIdx.x] = (ld < V) ? g_key[ld] : 0xFFFFFFFFFFFFFFFFull;
        __syncthreads();
        int lim = min(256, V - t0);
        for (int u = 0; u < lim; u++) r += (tile[u] < my);
        __syncthreads();
    }
    if (idx < V) {
        int k = (int)(my & 0xFFFFFFFFull);
        float t = __uint_as_float((unsigned)(my >> 32));
        float w = W1a[k], b = b1a[k];
        g_tS[r] = t;
        g_kS[r] = k;
        if (w > 0.f) { g_cw[r] = w;  g_cb[r] = b;  }
        else         { g_cw[r] = -w; g_cb[r] = -b; }
    }
}

// ------------- baseline partial sums (smem-staged, unrolled gather) ----------
#define BMAXC 272   // max rows per baseline chunk: ceil(8320/32)+pad
__global__ void __launch_bounds__(128) k_baseline(const float* __restrict__ W1a,
                                                  const float* __restrict__ b1a,
                                                  const float* __restrict__ W1b) {
    int col = blockIdx.x * 128 + threadIdx.x;
    int c = blockIdx.y;
    int nB = g_cntB;
    int lo = (c * nB) / BCH, hi = ((c + 1) * nB) / BCH;
    int cnt = hi - lo;
    __shared__ int   sk[BMAXC];
    __shared__ float sw[BMAXC], sb[BMAXC];
    for (int i = threadIdx.x; i < cnt; i += 128) {
        int k = g_kB[lo + i];
        sk[i] = k;
        sw[i] = W1a[k];
        sb[i] = b1a[k];
    }
    __syncthreads();
    float s = 0.f, q = 0.f;
    int r = 0;
    for (; r + 4 <= cnt; r += 4) {
        float v0 = W1b[(size_t)sk[r + 0] * DH + col];
        float v1 = W1b[(size_t)sk[r + 1] * DH + col];
        float v2 = W1b[(size_t)sk[r + 2] * DH + col];
        float v3 = W1b[(size_t)sk[r + 3] * DH + col];
        s = fmaf(sw[r + 0], v0, s); q = fmaf(sb[r + 0], v0, q);
        s = fmaf(sw[r + 1], v1, s); q = fmaf(sb[r + 1], v1, q);
        s = fmaf(sw[r + 2], v2, s); q = fmaf(sb[r + 2], v2, q);
        s = fmaf(sw[r + 3], v3, s); q = fmaf(sb[r + 3], v3, q);
    }
    for (; r < cnt; r++) {
        float v = W1b[(size_t)sk[r] * DH + col];
        s = fmaf(sw[r], v, s);
        q = fmaf(sb[r], v, q);
    }
    g_BpS[c][col] = s;
    g_BpQ[c][col] = q;
}

// ------------- chunked local prefix scan (smem-staged, unrolled) --------------
#define PMAXC 560   // max rows per prefix chunk: ceil((8320+16)/16)+pad
__global__ void __launch_bounds__(128) k_prefix(const float* __restrict__ W1b) {
    int col = blockIdx.x * 128 + threadIdx.x;
    int c = blockIdx.y;
    int L = g_L, V = g_cntV;
    int base = c * L;
    __shared__ int   sk[PMAXC];
    __shared__ float sw[PMAXC], sb[PMAXC];
    for (int i = threadIdx.x; i < L; i += 128) {
        int j = base + i;
        if (j < V) {
            sk[i] = g_kS[j];
            sw[i] = g_cw[j];
            sb[i] = g_cb[j];
        } else {
            sk[i] = 0; sw[i] = 0.f; sb[i] = 0.f;
        }
    }
    __syncthreads();
    float s = 0.f, q = 0.f;
    float* outS = g_SLs + (size_t)base * DH + col;
    float* outQ = g_SLq + (size_t)base * DH + col;
    int jl = 0;
    for (; jl + 4 <= L; jl += 4) {
        float v0 = W1b[(size_t)sk[jl + 0] * DH + col];
        float v1 = W1b[(size_t)sk[jl + 1] * DH + col];
        float v2 = W1b[(size_t)sk[jl + 2] * DH + col];
        float v3 = W1b[(size_t)sk[jl + 3] * DH + col];
        outS[(size_t)(jl + 0) * DH] = s; outQ[(size_t)(jl + 0) * DH] = q;
        s = fmaf(sw[jl + 0], v0, s); q = fmaf(sb[jl + 0], v0, q);
        outS[(size_t)(jl + 1) * DH] = s; outQ[(size_t)(jl + 1) * DH] = q;
        s = fmaf(sw[jl + 1], v1, s); q = fmaf(sb[jl + 1], v1, q);
        outS[(size_t)(jl + 2) * DH] = s; outQ[(size_t)(jl + 2) * DH] = q;
        s = fmaf(sw[jl + 2], v2, s); q = fmaf(sb[jl + 2], v2, q);
        outS[(size_t)(jl + 3) * DH] = s; outQ[(size_t)(jl + 3) * DH] = q;
        s = fmaf(sw[jl + 3], v3, s); q = fmaf(sb[jl + 3], v3, q);
    }
    for (; jl < L; jl++) {
        float v = W1b[(size_t)sk[jl] * DH + col];
        outS[(size_t)jl * DH] = s; outQ[(size_t)jl * DH] = q;
        s = fmaf(sw[jl], v, s);
        q = fmaf(sb[jl], v, q);
    }
    g_TotS[c][col] = s;
    g_TotQ[c][col] = q;
}

// ------------- combine baseline + chunk totals into per-chunk offsets --------
__global__ void k_off() {
    int col = blockIdx.x * 128 + threadIdx.x;
    float sS = 0.f, sQ = 0.f;
    for (int bc = 0; bc < BCH; bc++) { sS += g_BpS[bc][col]; sQ += g_BpQ[bc][col]; }
    float oS = sS, oQ = sQ;
    for (int c = 0; c < VCH; c++) {
        g_OffS[c][col] = oS;
        g_OffQ[c][col] = oQ;
        oS += g_TotS[c][col];
        oQ += g_TotQ[c][col];
    }
}

// ------------- per-edge position: j = #(t <= a) -------------------------------
__global__ void k_edgej(const float* __restrict__ ea) {
    int e = blockIdx.x * 256 + threadIdx.x;
    if (e >= NEDGE) return;
    float a = ea[e];
    int lo = 0, hi = g_cntV;
    while (lo < hi) {
        int mid = (lo + hi) >> 1;
        if (g_tS[mid] <= a) lo = mid + 1; else hi = mid;
    }
    g_j[e] = lo;
}

// ---------------- c1[n,o] = sum_i x[n,i] * b1b[i*64+o] ------------------------
__global__ void k_c1(const float* __restrict__ x, const float* __restrict__ b1b) {
    int n = blockIdx.x, o = threadIdx.x;   // 64 threads
    __shared__ float xs[DFEAT];
    for (int i = o; i < DFEAT; i += HDIM) xs[i] = x[n * DFEAT + i];
    __syncthreads();
    float a = 0.f;
    for (int i = 0; i < DFEAT; i++) a = fmaf(xs[i], b1b[i * HDIM + o], a);
    g_c1[n * HDIM + o] = a;
}

// ------------- conv1 per-edge message via prefix rows -------------------------
__global__ void __launch_bounds__(128) k_msg1(const int* __restrict__ ei,
                                              const float* __restrict__ ea,
                                              const float* __restrict__ x) {
    int e = blockIdx.x;
    int tid = threadIdx.x;
    int src = ei[e];
    float a = ea[e];
    int j = g_j[e];
    int c = j / g_L;

    __shared__ float xs[DFEAT];
    __shared__ float rs[128], rq[128];
    for (int i = tid; i < DFEAT; i += 128) xs[i] = x[src * DFEAT + i];
    __syncthreads();

    int half = tid >> 6;
    int o = tid & 63;
    const float* Srow = g_SLs + (size_t)j * DH;
    const float* Qrow = g_SLq + (size_t)j * DH;
    const float* OfS = g_OffS[c];
    const float* OfQ = g_OffQ[c];

    float ss = 0.f, qq = 0.f;
#pragma unroll 5
    for (int i = half; i < DFEAT; i += 2) {
        int m = i * HDIM + o;
        float xi = xs[i];
        ss = fmaf(xi, Srow[m] + OfS[m], ss);
        qq = fmaf(xi, Qrow[m] + OfQ[m], qq);
    }
    rs[tid] = ss; rq[tid] = qq;
    __syncthreads();
    if (tid < 64) {
        float S = rs[tid] + rs[tid + 64];
        float Q = rq[tid] + rq[tid + 64];
        g_msg1[e * HDIM + tid] = fmaf(a, S, Q) + g_c1[src * HDIM + tid];
    }
}

// ------------- agg (mean over dst) + root weight + bias + relu -> h1 ---------
__global__ void k_agg_h1(const float* __restrict__ x,
                         const float* __restrict__ Wr1, const float* __restrict__ bc1) {
    int n = blockIdx.x, o = threadIdx.x;   // 64 threads
    __shared__ float xs[DFEAT];
    for (int i = o; i < DFEAT; i += HDIM) xs[i] = x[n * DFEAT + i];
    int beg = g_dstOff[n];
    int m = g_dstOff[n + 1] - beg;
    float a = 0.f;
    for (int jj = 0; jj < m; jj++) {
        int e = g_dstSorted[beg + jj];
        a += g_msg1[e * HDIM + o];
    }
    a /= fmaxf((float)m, 1.f);
    __syncthreads();
    float r = bc1[o];
    for (int i = 0; i < DFEAT; i++) r = fmaf(xs[i], Wr1[i * HDIM + o], r);
    g_h1[n * HDIM + o] = fmaxf(a + r, 0.f);
}

// ------------- conv2 pre-contraction: G2[n,k,o], c2[n,o] ----------------------
__global__ void k_G2c2(const float* __restrict__ W2b, const float* __restrict__ b2b) {
    int n = blockIdx.x;
    __shared__ float hs[HDIM];
    if (threadIdx.x < HDIM) hs[threadIdx.x] = g_h1[n * HDIM + threadIdx.x];
    __syncthreads();
    int k = threadIdx.x >> 2;
    int ob = (threadIdx.x & 3) * 16;
    float acc[16];
#pragma unroll
    for (int jj = 0; jj < 16; jj++) acc[jj] = 0.f;
    for (int i = 0; i < HDIM; i++) {
        float hv = hs[i];
        const float4* wr = (const float4*)(W2b + (size_t)k * (HDIM * HDIM) + i * HDIM + ob);
#pragma unroll
        for (int q = 0; q < 4; q++) {
            float4 w4 = wr[q];
            acc[q * 4 + 0] = fmaf(hv, w4.x, acc[q * 4 + 0]);
            acc[q * 4 + 1] = fmaf(hv, w4.y, acc[q * 4 + 1]);
            acc[q * 4 + 2] = fmaf(hv, w4.z, acc[q * 4 + 2]);
            acc[q * 4 + 3] = fmaf(hv, w4.w, acc[q * 4 + 3]);
        }
    }
    float* dst = g_G2 + ((size_t)n * HDIM + k) * HDIM + ob;
#pragma unroll
    for (int jj = 0; jj < 16; jj++) dst[jj] = acc[jj];
    if (threadIdx.x < HDIM) {
        int o = threadIdx.x;
        float cacc = 0.f;
        for (int i = 0; i < HDIM; i++) cacc = fmaf(hs[i], b2b[i * HDIM + o], cacc);
        g_c2[n * HDIM + o] = cacc;
    }
}

// ------------- conv2 per-edge message ----------------------------------------
__global__ void k_msg2(const int* __restrict__ ei, const float* __restrict__ ea,
                       const float* __restrict__ W2a, const float* __restrict__ b2a) {
    int e = blockIdx.x, o = threadIdx.x;   // 64 threads
    int s = ei[e];
    float a_ = ea[e];
    __shared__ float u2[HDIM];
    u2[o] = fmaxf(fmaf(a_, W2a[o], b2a[o]), 0.f);
    __syncthreads();
    float acc = g_c2[s * HDIM + o];
    const float* G2 = g_G2 + (size_t)s * HDIM * HDIM;
#pragma unroll 8
    for (int k = 0; k < HDIM; k++) acc = fmaf(u2[k], G2[k * HDIM + o], acc);
    g_msg2[e * HDIM + o] = acc;
}

// ------------- conv2 aggregation + root + relu -> h2 --------------------------
__global__ void k_agg2_h2(const float* __restrict__ Wr2, const float* __restrict__ bc2) {
    int n = blockIdx.x, o = threadIdx.x;   // 64 threads
    __shared__ float hs[HDIM];
    hs[o] = g_h1[n * HDIM + o];
    int beg = g_dstOff[n];
    int m = g_dstOff[n + 1] - beg;
    float a = 0.f;
    for (int jj = 0; jj < m; jj++) {
        int e = g_dstSorted[beg + jj];
        a += g_msg2[e * HDIM + o];
    }
    a /= fmaxf((float)m, 1.f);
    __syncthreads();
    float r = bc2[o];
    for (int i = 0; i < HDIM; i++) r = fmaf(hs[i], Wr2[i * HDIM + o], r);
    g_h2[n * HDIM + o] = fmaxf(a + r, 0.f);
}

// ------------- output head: logits -> masked softmax -> packet mask ----------
__global__ void k_out(const int* __restrict__ adj, const float* __restrict__ npk,
                      const float* __restrict__ Wout, const float* __restrict__ bout,
                      float* __restrict__ out) {
    int n = blockIdx.x, j = threadIdx.x;   // 128 threads
    __shared__ float hs[HDIM];
    __shared__ float red[NNODE];
    if (j < HDIM) hs[j] = g_h2[n * HDIM + j];
    __syncthreads();
    float l = bout[j];
    for (int o = 0; o < HDIM; o++) l = fmaf(hs[o], Wout[o * NNODE + j], l);
    bool a = (adj[n * NNODE + j] != 0);
    const float NEGINF = __int_as_float(0xff800000);
    red[j] = a ? l : NEGINF;
    __syncthreads();
    for (int s = 64; s > 0; s >>= 1) {
        if (j < s) red[j] = fmaxf(red[j], red[j + s]);
        __syncthreads();
    }
    float mx = red[0];
    __syncthreads();
    float p = a ? expf(l - mx) : 0.f;
    red[j] = p;
    __syncthreads();
    for (int s = 64; s > 0; s >>= 1) {
        if (j < s) red[j] += red[j + s];
        __syncthreads();
    }
    float sum = red[0];
    float pr = p / sum;
    bool msk = (npk[n] != -1.0f);
    out[n * NNODE + j] = msk ? pr : (j == n ? 1.f : 0.f);
}

// ------------------------------ launcher --------------------------------------
extern "C" void kernel_launch(void* const* d_in, const int* in_sizes, int n_in,
                              void* d_out, int out_size) {
    const float* x    = (const float*)d_in[0];
    const int*   ei   = (const int*)  d_in[1];
    const float* ea   = (const float*)d_in[2];
    const int*   adj  = (const int*)  d_in[3];
    const float* npk  = (const float*)d_in[4];
    const float* W1a  = (const float*)d_in[5];
    const float* b1a  = (const float*)d_in[6];
    const float* W1b  = (const float*)d_in[7];
    const float* b1b  = (const float*)d_in[8];
    const float* Wr1  = (const float*)d_in[9];
    const float* bc1  = (const float*)d_in[10];
    const float* W2a  = (const float*)d_in[11];
    const float* b2a  = (const float*)d_in[12];
    const float* W2b  = (const float*)d_in[13];
    const float* b2b  = (const float*)d_in[14];
    const float* Wr2  = (const float*)d_in[15];
    const float* bc2  = (const float*)d_in[16];
    const float* Wout = (const float*)d_in[17];
    const float* bout = (const float*)d_in[18];
    float* out = (float*)d_out;

    k_offsets<<<1, 128>>>(ei);
    k_fill<<<1, 256>>>(ei);
    k_classify<<<1, 256>>>(W1a, b1a);
    k_rank<<<(DH + 255) / 256, 256>>>(W1a, b1a);
    k_baseline<<<dim3(65, BCH), 128>>>(W1a, b1a, W1b);
    k_prefix<<<dim3(65, VCH), 128>>>(W1b);
    k_off<<<65, 128>>>();
    k_edgej<<<16, 256>>>(ea);
    k_c1<<<NNODE, HDIM>>>(x, b1b);
    k_msg1<<<NEDGE, 128>>>(ei, ea, x);
    k_agg_h1<<<NNODE, HDIM>>>(x, Wr1, bc1);
    k_G2c2<<<NNODE, 256>>>(W2b, b2b);
    k_msg2<<<NEDGE, HDIM>>>(ei, ea, W2a, b2a);
    k_agg2_h2<<<NNODE, HDIM>>>(Wr2, bc2);
    k_out<<<NNODE, NNODE>>>(adj, npk, Wout, bout, out);
}